// round 15
// baseline (speedup 1.0000x reference)
#include <cuda_runtime.h>
#include <cuda_fp16.h>
#include <cstdint>

#define B_ 8
#define E_ 2048
#define N_ 2048
#define F_ 128

// Y = X @ W^T stored transposed [b][f][n], single fp16 (device scratch).
__device__ __align__(16) __half g_Y[B_ * F_ * N_];

extern __shared__ __align__(16) char g_smem[];

// ---------------- helpers ----------------
__device__ __forceinline__ uint32_t smem_u32(const void* p) {
    uint32_t a;
    asm("{ .reg .u64 t; cvta.to.shared.u64 t, %1; cvt.u32.u64 %0, t; }" : "=r"(a) : "l"(p));
    return a;
}
__device__ __forceinline__ uint32_t h2_as_u32(__half2 h) {
    uint32_t u;
    asm("mov.b32 %0, %1;" : "=r"(u) : "r"(*(uint32_t*)&h));
    return u;
}
__device__ __forceinline__ float4 ldcs4(const float* p) {
    float4 v;
    asm("ld.global.cs.v4.f32 {%0,%1,%2,%3}, [%4];"
        : "=f"(v.x), "=f"(v.y), "=f"(v.z), "=f"(v.w) : "l"(p));
    return v;
}
#define SWZ(x) ((x) ^ (((x) >> 3) & 0x70))

#define CP16(dst, src) \
    asm volatile("cp.async.ca.shared.global [%0], [%1], 16;" :: "r"(dst), "l"(src))
#define CP_COMMIT() asm volatile("cp.async.commit_group;" ::: "memory")
#define CP_WAIT1()  asm volatile("cp.async.wait_group 1;" ::: "memory")
#define CP_WAIT0()  asm volatile("cp.async.wait_group 0;" ::: "memory")

#define LDSM_X4(r0, r1, r2, r3, addr) \
    asm volatile("ldmatrix.sync.aligned.m8n8.x4.shared.b16 {%0,%1,%2,%3}, [%4];" \
                 : "=r"(r0), "=r"(r1), "=r"(r2), "=r"(r3) : "r"(addr))

#define MMA_F16(d, a, b0, b1) \
    asm volatile("mma.sync.aligned.m16n8k16.row.col.f32.f16.f16.f32 " \
                 "{%0,%1,%2,%3}, {%4,%5,%6,%7}, {%8,%9}, {%0,%1,%2,%3};" \
                 : "+f"((d)[0]), "+f"((d)[1]), "+f"((d)[2]), "+f"((d)[3]) \
                 : "r"((a)[0]), "r"((a)[1]), "r"((a)[2]), "r"((a)[3]), \
                   "r"(b0), "r"(b1))

__device__ __forceinline__ void sts64(uint32_t a, uint32_t x, uint32_t y) {
    asm volatile("st.shared.v2.b32 [%0], {%1, %2};" :: "r"(a), "r"(x), "r"(y));
}

// Expand 2 mask-row words into an ldmatrix.x4-ordered fp16 A fragment.
// w0/w1: 32-bit halves of rows r and r+8; sh: base bit = (lid&3)*2 (+16 for odd kb).
#define EXPAND_A(areg_, w0_, w1_, sh_)                                         \
    do {                                                                       \
        uint32_t t0_ = (w0_) >> (sh_), t1_ = (w1_) >> (sh_);                   \
        (areg_)[0] = ((t0_ & 1u) * 0x3C00u) | ((t0_ & 2u) * 0x1E000000u);      \
        (areg_)[1] = ((t1_ & 1u) * 0x3C00u) | ((t1_ & 2u) * 0x1E000000u);      \
        t0_ >>= 8; t1_ >>= 8;                                                  \
        (areg_)[2] = ((t0_ & 1u) * 0x3C00u) | ((t0_ & 2u) * 0x1E000000u);      \
        (areg_)[3] = ((t1_ & 1u) * 0x3C00u) | ((t1_ & 2u) * 0x1E000000u);      \
    } while (0)

// ---------------- Prologue: Y = fp16(X) @ fp16(W)^T via mma.sync (unchanged R14) ----------------
__global__ void __launch_bounds__(256) v2h_prologue(const float* __restrict__ X,
                                                    const float* __restrict__ W) {
    uint32_t sb = smem_u32(g_smem);
    const uint32_t WhB = sb;             // 2 x 16384
    const uint32_t XhB = sb + 32768u;    // 2 x 16384
    int t = threadIdx.x, lid = t & 31, wid = t >> 5;
    int warpM = wid >> 2, warpN = wid & 3;
    int b = blockIdx.x >> 4, n0 = (blockIdx.x & 15) << 7;

    {
        int row = t >> 1, seg = t & 1;
        const float* wp = W + (size_t)row * F_ + seg * 64;
        const float* xp = X + ((size_t)(b * N_ + n0 + row)) * F_ + seg * 64;
        uint32_t wdst = WhB + (uint32_t)seg * 16384u;
        uint32_t xdst = XhB + (uint32_t)seg * 16384u;
#pragma unroll
        for (int q = 0; q < 16; q++) {
            float4 wv = ldcs4(wp + q * 4);
            float4 xv = ldcs4(xp + q * 4);
            uint32_t off = SWZ((uint32_t)(row * 128 + q * 8));
            sts64(wdst + off, h2_as_u32(__floats2half2_rn(wv.x, wv.y)),
                              h2_as_u32(__floats2half2_rn(wv.z, wv.w)));
            sts64(xdst + off, h2_as_u32(__floats2half2_rn(xv.x, xv.y)),
                              h2_as_u32(__floats2half2_rn(xv.z, xv.w)));
        }
    }
    __syncthreads();

    float acc[4][4][4];
#pragma unroll
    for (int m = 0; m < 4; m++)
#pragma unroll
        for (int n = 0; n < 4; n++)
#pragma unroll
            for (int v = 0; v < 4; v++) acc[m][n][v] = 0.f;

    const uint32_t r16 = (uint32_t)(lid & 15), kb0 = (uint32_t)(lid >> 4);

#pragma unroll
    for (int kb = 0; kb < 8; kb++) {
        uint32_t kbuf = (uint32_t)(kb >> 2) * 16384u;
        uint32_t ko = (((uint32_t)kb & 3u) * 2u + kb0) * 16u;
        uint32_t bx[2][4];
#pragma unroll
        for (int g = 0; g < 2; g++) {
            uint32_t row = (uint32_t)(warpN * 32 + g * 16) + r16;
            LDSM_X4(bx[g][0], bx[g][1], bx[g][2], bx[g][3],
                    XhB + kbuf + SWZ(row * 128 + ko));
        }
#pragma unroll
        for (int mt = 0; mt < 4; mt++) {
            uint32_t row = (uint32_t)(warpM * 64 + mt * 16) + r16;
            uint32_t aw[4];
            LDSM_X4(aw[0], aw[1], aw[2], aw[3], WhB + kbuf + SWZ(row * 128 + ko));
            MMA_F16(acc[mt][0], aw, bx[0][0], bx[0][2]);
            MMA_F16(acc[mt][1], aw, bx[0][1], bx[0][3]);
            MMA_F16(acc[mt][2], aw, bx[1][0], bx[1][2]);
            MMA_F16(acc[mt][3], aw, bx[1][1], bx[1][3]);
        }
    }

    __half* Yb = g_Y + (size_t)b * F_ * N_;
#pragma unroll
    for (int mt = 0; mt < 4; mt++) {
        int f = warpM * 64 + mt * 16 + (lid >> 2);
#pragma unroll
        for (int nt = 0; nt < 4; nt++) {
            int n = n0 + warpN * 32 + nt * 8 + (lid & 3) * 2;
            float* d = acc[mt][nt];
            *(uint32_t*)(Yb + (size_t)f * N_ + n) =
                h2_as_u32(__floats2half2_rn(d[0], d[1]));
            *(uint32_t*)(Yb + (size_t)(f + 8) * N_ + n) =
                h2_as_u32(__floats2half2_rn(d[2], d[3]));
        }
    }
}

// ---------------- Main: out = relu((mask @ Y)/norm + b) ----------------
// grid 256 = b*32 + etile(64 rows); 256 thr = 8 warps (2M x 4N), 2 CTAs/SM.
// 32 stages of K=64. Mask stored as 64-bit row words (2x512B smem),
// A fragments ALU-expanded; Y triple-buffered cp.async; one sync/stage.
__global__ void __launch_bounds__(256, 2) v2h_main(const float* __restrict__ adj,
                                                   const float* __restrict__ bias,
                                                   float* __restrict__ out) {
    uint32_t sb = smem_u32(g_smem);
    float* sNorm = (float*)g_smem;                      // 64 floats @ 0
    // mask words @ 256: 2 buffers x 64 rows x 8 B
    const uint32_t yBase = (sb + 1280u + 1023u) & ~1023u;  // 3 x 16384 Y fp16
    int t = threadIdx.x, lid = t & 31, wid = t >> 5;
    int warpM = wid >> 2, warpN = wid & 3;
    int b = blockIdx.x >> 5, e0 = (blockIdx.x & 31) << 6;

    int r = t >> 2, seg = t & 3;                         // convert: 4 thr/row, 16 k each
    const float* ap = adj + ((size_t)(b * E_ + e0 + r)) * N_ + seg * 16;
    const char* YG = (const char*)(g_Y + (size_t)b * F_ * N_);

    int cnt = 0;
    float4 ra[4];

#define CONVERT_BITS(bufsel_)                                                 \
    do {                                                                      \
        uint32_t bits_ = 0;                                                   \
        _Pragma("unroll")                                                     \
        for (int q_ = 0; q_ < 4; q_++) {                                      \
            float4 v_ = ra[q_];                                               \
            bits_ |= (v_.x == -1.f ? 1u : 0u) << (4 * q_);                    \
            bits_ |= (v_.y == -1.f ? 2u : 0u) << (4 * q_);                    \
            bits_ |= (v_.z == -1.f ? 4u : 0u) << (4 * q_);                    \
            bits_ |= (v_.w == -1.f ? 8u : 0u) << (4 * q_);                    \
        }                                                                     \
        cnt += __popc(bits_);                                                 \
        ((uint16_t*)(g_smem + 256 + (bufsel_) * 512))[r * 4 + seg] =          \
            (uint16_t)bits_;                                                  \
    } while (0)

#define CP_Y(stage_)                                                          \
    do {                                                                      \
        uint32_t yb_ = yBase + (uint32_t)((stage_) % 3) * 16384u;             \
        size_t ko_ = (size_t)(stage_) * 64;                                   \
        _Pragma("unroll")                                                     \
        for (int i_ = 0; i_ < 4; i_++) {                                      \
            int cid_ = t + i_ * 256, rw_ = cid_ >> 3, j_ = cid_ & 7;          \
            CP16(yb_ + SWZ((uint32_t)(rw_ * 128 + j_ * 16)),                  \
                 YG + ((size_t)rw_ * N_ + ko_ + j_ * 8) * 2);                 \
        }                                                                     \
        CP_COMMIT();                                                          \
    } while (0)

    // ---- pipeline prologue ----
#pragma unroll
    for (int q = 0; q < 4; q++) ra[q] = ldcs4(ap + q * 4);   // stage 0
    CONVERT_BITS(0);
    CP_Y(0);
    ap += 64;
#pragma unroll
    for (int q = 0; q < 4; q++) ra[q] = ldcs4(ap + q * 4);   // stage 1
    CP_Y(1);

    float acc[2][4][4];
#pragma unroll
    for (int m = 0; m < 2; m++)
#pragma unroll
        for (int n = 0; n < 4; n++)
#pragma unroll
            for (int v = 0; v < 4; v++) acc[m][n][v] = 0.f;

    const uint32_t r16 = (uint32_t)(lid & 15), kb0 = (uint32_t)(lid >> 4);
    const uint32_t s0 = (uint32_t)((lid & 3) * 2);

    for (int s = 0; s < 32; s++) {
        uint32_t yB = yBase + (uint32_t)(s % 3) * 16384u;
        if (s < 31) CP_WAIT1(); else CP_WAIT0();
        __syncthreads();   // stage-s mask words + Y visible; s+1/s+2 buffers free

        // load this stage's 4 mask-row words (rows warpM*32 + q*8 + lid>>2)
        uint2 mw[4];
        {
            const uint2* mrow = (const uint2*)(g_smem + 256 + (s & 1) * 512);
#pragma unroll
            for (int q = 0; q < 4; q++)
                mw[q] = mrow[warpM * 32 + q * 8 + (lid >> 2)];
        }

        if (s < 31) CONVERT_BITS((s + 1) & 1);
        if (s < 30) {
            ap += 64;
#pragma unroll
            for (int q = 0; q < 4; q++) ra[q] = ldcs4(ap + q * 4);  // stage s+2
            CP_Y(s + 2);
        }

#pragma unroll
        for (int kb = 0; kb < 4; kb++) {
            uint32_t sh = s0 + (uint32_t)(kb & 1) * 16u;
            uint32_t koffb = ((uint32_t)kb * 2 + kb0) * 16;
            uint32_t bh[2][4];
#pragma unroll
            for (int g = 0; g < 2; g++) {
                uint32_t row = (uint32_t)(warpN * 32 + g * 16) + r16;
                LDSM_X4(bh[g][0], bh[g][1], bh[g][2], bh[g][3],
                        yB + SWZ(row * 128 + koffb));
            }
            uint32_t a_[2][4];
            if (kb < 2) {
                EXPAND_A(a_[0], mw[0].x, mw[1].x, sh);
                EXPAND_A(a_[1], mw[2].x, mw[3].x, sh);
            } else {
                EXPAND_A(a_[0], mw[0].y, mw[1].y, sh);
                EXPAND_A(a_[1], mw[2].y, mw[3].y, sh);
            }
#pragma unroll
            for (int mt = 0; mt < 2; mt++)
#pragma unroll
                for (int g = 0; g < 2; g++) {
                    MMA_F16(acc[mt][2 * g],     a_[mt], bh[g][0], bh[g][2]);
                    MMA_F16(acc[mt][2 * g + 1], a_[mt], bh[g][1], bh[g][3]);
                }
        }
    }

    // norm: quad-reduce (4 threads per row share r = t>>2)
    {
        int c = cnt;
        c += __shfl_xor_sync(0xFFFFFFFFu, c, 1);
        c += __shfl_xor_sync(0xFFFFFFFFu, c, 2);
        if ((lid & 3) == 0) sNorm[r] = (float)(c ? c : 1);
    }
    __syncthreads();

#pragma unroll
    for (int mt = 0; mt < 2; mt++) {
        int lr = warpM * 32 + mt * 16 + (lid >> 2);
        float i0 = 1.0f / sNorm[lr];
        float i1 = 1.0f / sNorm[lr + 8];
        float* o0 = out + ((size_t)(b * E_ + e0 + lr)) * F_;
        float* o1 = o0 + 8 * F_;
#pragma unroll
        for (int nt = 0; nt < 4; nt++) {
            int col = warpN * 32 + nt * 8 + (lid & 3) * 2;
            float2 bb = *(const float2*)(bias + col);
            float* d = acc[mt][nt];
            float2 v0, v1;
            v0.x = fmaxf(fmaf(d[0], i0, bb.x), 0.f);
            v0.y = fmaxf(fmaf(d[1], i0, bb.y), 0.f);
            v1.x = fmaxf(fmaf(d[2], i1, bb.x), 0.f);
            v1.y = fmaxf(fmaf(d[3], i1, bb.y), 0.f);
            *(float2*)(o0 + col) = v0;
            *(float2*)(o1 + col) = v1;
        }
    }
}

extern "C" void kernel_launch(void* const* d_in, const int* in_sizes, int n_in,
                              void* d_out, int out_size) {
    const float* X    = (const float*)d_in[0];  // [B,N,F]
    const float* adj  = (const float*)d_in[1];  // [B,E,N]
    const float* W    = (const float*)d_in[2];  // [F,F]
    const float* bias = (const float*)d_in[3];  // [F]
    float* out = (float*)d_out;                 // [B,E,F]
    (void)in_sizes; (void)n_in; (void)out_size;

    const int smem_pro  = 65536;                 // Wh 32K + Xh 32K
    const int smem_main = 2048 + 3 * 16384 + 1024;  // 52224 (norm+masks+align+Y)
    cudaFuncSetAttribute(v2h_prologue, cudaFuncAttributeMaxDynamicSharedMemorySize, smem_pro);
    cudaFuncSetAttribute(v2h_main,     cudaFuncAttributeMaxDynamicSharedMemorySize, smem_main);

    v2h_prologue<<<128, 256, smem_pro>>>(X, W);
    v2h_main<<<256, 256, smem_main>>>(adj, bias, out);
}

// round 16
// speedup vs baseline: 1.1754x; 1.1754x over previous
#include <cuda_runtime.h>
#include <cuda_fp16.h>
#include <cstdint>

#define B_ 8
#define E_ 2048
#define N_ 2048
#define F_ 128

// Y = X @ W^T stored transposed [b][f][n], single fp16 (device scratch).
__device__ __align__(16) __half g_Y[B_ * F_ * N_];
// per-(batch, 64-col shard) ready flags
__device__ int g_flags[B_ * 32];

extern __shared__ __align__(16) char g_smem[];

// ---------------- helpers ----------------
__device__ __forceinline__ uint32_t smem_u32(const void* p) {
    uint32_t a;
    asm("{ .reg .u64 t; cvta.to.shared.u64 t, %1; cvt.u32.u64 %0, t; }" : "=r"(a) : "l"(p));
    return a;
}
__device__ __forceinline__ uint32_t h2_as_u32(__half2 h) {
    uint32_t u;
    asm("mov.b32 %0, %1;" : "=r"(u) : "r"(*(uint32_t*)&h));
    return u;
}
__device__ __forceinline__ float4 ldcs4(const float* p) {
    float4 v;
    asm("ld.global.cs.v4.f32 {%0,%1,%2,%3}, [%4];"
        : "=f"(v.x), "=f"(v.y), "=f"(v.z), "=f"(v.w) : "l"(p));
    return v;
}
__device__ __forceinline__ void wait_flag(const int* f) {
    int v;
    do {
        asm volatile("ld.acquire.gpu.global.u32 %0, [%1];" : "=r"(v) : "l"(f));
    } while (!v);
}
#define SWZ(x) ((x) ^ (((x) >> 3) & 0x70))

#define CP16(dst, src) \
    asm volatile("cp.async.ca.shared.global [%0], [%1], 16;" :: "r"(dst), "l"(src))
#define CP_COMMIT() asm volatile("cp.async.commit_group;" ::: "memory")
#define CP_WAIT1()  asm volatile("cp.async.wait_group 1;" ::: "memory")
#define CP_WAIT0()  asm volatile("cp.async.wait_group 0;" ::: "memory")

#define LDSM_X4(r0, r1, r2, r3, addr) \
    asm volatile("ldmatrix.sync.aligned.m8n8.x4.shared.b16 {%0,%1,%2,%3}, [%4];" \
                 : "=r"(r0), "=r"(r1), "=r"(r2), "=r"(r3) : "r"(addr))

#define MMA_F16(d, a, b0, b1) \
    asm volatile("mma.sync.aligned.m16n8k16.row.col.f32.f16.f16.f32 " \
                 "{%0,%1,%2,%3}, {%4,%5,%6,%7}, {%8,%9}, {%0,%1,%2,%3};" \
                 : "+f"((d)[0]), "+f"((d)[1]), "+f"((d)[2]), "+f"((d)[3]) \
                 : "r"((a)[0]), "r"((a)[1]), "r"((a)[2]), "r"((a)[3]), \
                   "r"(b0), "r"(b1))

__device__ __forceinline__ void sts64(uint32_t a, uint32_t x, uint32_t y) {
    asm volatile("st.shared.v2.b32 [%0], {%1, %2};" :: "r"(a), "r"(x), "r"(y));
}
__device__ __forceinline__ void sts128(uint32_t a, uint4 v) {
    asm volatile("st.shared.v4.b32 [%0], {%1, %2, %3, %4};"
                 :: "r"(a), "r"(v.x), "r"(v.y), "r"(v.z), "r"(v.w));
}
__device__ __forceinline__ uint32_t mask2(float x, float y) {
    return (x == -1.f ? 0x3C00u : 0u) | (y == -1.f ? 0x3C000000u : 0u);
}

// ---------------- flag clear (runs first each replay) ----------------
__global__ void v2h_clear() { g_flags[threadIdx.x] = 0; }

// ---------------- Fused kernel ----------------
// grid 256 = b*32 + tile. Phase A: compute Y[b][:, tile*64 .. +64) via HMMA,
// publish flag. Phase B: R14 main loop over e-tile (64 rows = same index),
// waiting on flag[b][stage] before each stage's Y cp.async.
__global__ void __launch_bounds__(256, 2) v2h_fused(const float* __restrict__ X,
                                                    const float* __restrict__ W,
                                                    const float* __restrict__ adj,
                                                    const float* __restrict__ bias,
                                                    float* __restrict__ out) {
    uint32_t sb = smem_u32(g_smem);
    const uint32_t tb = (sb + 256u + 1023u) & ~1023u;
    int t = threadIdx.x, lid = t & 31, wid = t >> 5;
    int warpM = wid >> 2, warpN = wid & 3;               // 2 x 4
    int b = blockIdx.x >> 5, tile = blockIdx.x & 31;
    int e0 = tile << 6, n0 = tile << 6;
    int* flagB = g_flags + b * 32;

    // ======== Phase A: Y shard GEMM (D = W @ Xshard^T, rows = f) ========
    {
        const uint32_t WhB = tb;             // 2 x 16384 (k chunks of 64)
        const uint32_t XhB = tb + 32768u;    // 2 x 8192
        // load W full (2 thr/row, 64 k each) + X shard (4 thr/row, 32 k each)
        {
            int wrow = t >> 1, wseg = t & 1;
            const float* wp = W + (size_t)wrow * F_ + wseg * 64;
            uint32_t wdst = WhB + (uint32_t)wseg * 16384u;
#pragma unroll
            for (int q = 0; q < 16; q++) {
                float4 wv = *(const float4*)(wp + q * 4);
                sts64(wdst + SWZ((uint32_t)(wrow * 128 + q * 8)),
                      h2_as_u32(__floats2half2_rn(wv.x, wv.y)),
                      h2_as_u32(__floats2half2_rn(wv.z, wv.w)));
            }
            int xrow = t >> 2, xseg = t & 3;
            const float* xp = X + ((size_t)(b * N_ + n0 + xrow)) * F_ + xseg * 32;
            uint32_t xdst = XhB + (uint32_t)(xseg >> 1) * 8192u;
            uint32_t xko = (uint32_t)(xseg & 1) * 64u;
#pragma unroll
            for (int q = 0; q < 8; q++) {
                float4 xv = ldcs4(xp + q * 4);
                sts64(xdst + SWZ((uint32_t)(xrow * 128) + xko + q * 8),
                      h2_as_u32(__floats2half2_rn(xv.x, xv.y)),
                      h2_as_u32(__floats2half2_rn(xv.z, xv.w)));
            }
        }
        __syncthreads();

        float acc[4][2][4];
#pragma unroll
        for (int m = 0; m < 4; m++)
#pragma unroll
            for (int n = 0; n < 2; n++)
#pragma unroll
                for (int v = 0; v < 4; v++) acc[m][n][v] = 0.f;

        const uint32_t r16 = (uint32_t)(lid & 15), kb0 = (uint32_t)(lid >> 4);
#pragma unroll
        for (int kb = 0; kb < 8; kb++) {
            uint32_t wbuf = (uint32_t)(kb >> 2) * 16384u;
            uint32_t xbuf = (uint32_t)(kb >> 2) * 8192u;
            uint32_t ko = (((uint32_t)kb & 3u) * 2u + kb0) * 16u;
            uint32_t bx[4];
            {
                uint32_t row = (uint32_t)(warpN * 16) + r16;
                LDSM_X4(bx[0], bx[1], bx[2], bx[3], XhB + xbuf + SWZ(row * 128 + ko));
            }
#pragma unroll
            for (int mt = 0; mt < 4; mt++) {
                uint32_t row = (uint32_t)(warpM * 64 + mt * 16) + r16;
                uint32_t aw[4];
                LDSM_X4(aw[0], aw[1], aw[2], aw[3], WhB + wbuf + SWZ(row * 128 + ko));
                MMA_F16(acc[mt][0], aw, bx[0], bx[2]);
                MMA_F16(acc[mt][1], aw, bx[1], bx[3]);
            }
        }

        __half* Yb = g_Y + (size_t)b * F_ * N_;
#pragma unroll
        for (int mt = 0; mt < 4; mt++) {
            int f = warpM * 64 + mt * 16 + (lid >> 2);
#pragma unroll
            for (int nt = 0; nt < 2; nt++) {
                int n = n0 + warpN * 16 + nt * 8 + (lid & 3) * 2;
                float* d = acc[mt][nt];
                *(uint32_t*)(Yb + (size_t)f * N_ + n) =
                    h2_as_u32(__floats2half2_rn(d[0], d[1]));
                *(uint32_t*)(Yb + (size_t)(f + 8) * N_ + n) =
                    h2_as_u32(__floats2half2_rn(d[2], d[3]));
            }
        }
        __threadfence();
        __syncthreads();
        if (t == 0) {
            asm volatile("st.release.gpu.global.u32 [%0], %1;"
                         :: "l"(flagB + tile), "r"(1) : "memory");
        }
    }

    // ======== Phase B: out = relu((mask @ Y)/norm + b)  (R14 main) ========
    float* sNorm = (float*)g_smem;                       // 64 floats @ 0
    const uint32_t aBase = tb;                           // 2 x 8192 mask fp16
    const uint32_t yBase = tb + 16384u;                  // 3 x 16384 Y fp16

    int r = t >> 2, seg = t & 3;                          // convert: 4 thr/row, 16 k
    const float* ap = adj + ((size_t)(b * E_ + e0 + r)) * N_ + seg * 16;
    const char* YG = (const char*)(g_Y + (size_t)b * F_ * N_);
    const uint32_t stsOff = (uint32_t)(r * 128 + seg * 32);

    int cnt = 0;
    float4 ra[4];

#define CONVERT_STS(abuf_)                                                        \
    do {                                                                          \
        float4 v0 = ra[0], v1 = ra[1], v2 = ra[2], v3 = ra[3];                    \
        cnt += (v0.x == -1.f) + (v0.y == -1.f) + (v0.z == -1.f) + (v0.w == -1.f)  \
             + (v1.x == -1.f) + (v1.y == -1.f) + (v1.z == -1.f) + (v1.w == -1.f)  \
             + (v2.x == -1.f) + (v2.y == -1.f) + (v2.z == -1.f) + (v2.w == -1.f)  \
             + (v3.x == -1.f) + (v3.y == -1.f) + (v3.z == -1.f) + (v3.w == -1.f); \
        uint4 u0, u1;                                                             \
        u0.x = mask2(v0.x, v0.y); u0.y = mask2(v0.z, v0.w);                       \
        u0.z = mask2(v1.x, v1.y); u0.w = mask2(v1.z, v1.w);                       \
        u1.x = mask2(v2.x, v2.y); u1.y = mask2(v2.z, v2.w);                       \
        u1.z = mask2(v3.x, v3.y); u1.w = mask2(v3.z, v3.w);                       \
        sts128((abuf_) + SWZ(stsOff), u0);                                        \
        sts128((abuf_) + SWZ(stsOff + 16u), u1);                                  \
    } while (0)

#define CP_Y(stage_)                                                              \
    do {                                                                          \
        uint32_t yb_ = yBase + (uint32_t)((stage_) % 3) * 16384u;                 \
        size_t ko_ = (size_t)(stage_) * 64;                                       \
        _Pragma("unroll")                                                         \
        for (int i_ = 0; i_ < 4; i_++) {                                          \
            int cid_ = t + i_ * 256, rw_ = cid_ >> 3, j_ = cid_ & 7;              \
            CP16(yb_ + SWZ((uint32_t)(rw_ * 128 + j_ * 16)),                      \
                 YG + ((size_t)rw_ * N_ + ko_ + j_ * 8) * 2);                     \
        }                                                                         \
        CP_COMMIT();                                                              \
    } while (0)

#pragma unroll
    for (int q = 0; q < 4; q++) ra[q] = ldcs4(ap + q * 4);   // stage 0 adj
    CONVERT_STS(aBase);
    wait_flag(flagB + 0);
    CP_Y(0);
    ap += 64;
#pragma unroll
    for (int q = 0; q < 4; q++) ra[q] = ldcs4(ap + q * 4);   // stage 1 adj
    wait_flag(flagB + 1);
    CP_Y(1);

    float acc[2][4][4];
#pragma unroll
    for (int m = 0; m < 2; m++)
#pragma unroll
        for (int n = 0; n < 4; n++)
#pragma unroll
            for (int v = 0; v < 4; v++) acc[m][n][v] = 0.f;

    const uint32_t r16 = (uint32_t)(lid & 15), kb0 = (uint32_t)(lid >> 4);

    for (int s = 0; s < 32; s++) {
        uint32_t aB = aBase + (uint32_t)(s & 1) * 8192u;
        uint32_t yB = yBase + (uint32_t)(s % 3) * 16384u;
        if (s < 31) CP_WAIT1(); else CP_WAIT0();
        __syncthreads();
        if (s < 31) CONVERT_STS(aBase + (uint32_t)((s + 1) & 1) * 8192u);
        if (s < 30) {
            ap += 64;
#pragma unroll
            for (int q = 0; q < 4; q++) ra[q] = ldcs4(ap + q * 4);
            wait_flag(flagB + (s + 2));
            CP_Y(s + 2);
        }

#pragma unroll
        for (int kb = 0; kb < 4; kb++) {
            uint32_t koffb = ((uint32_t)kb * 2 + kb0) * 16;
            uint32_t a_[2][4];
#pragma unroll
            for (int mt = 0; mt < 2; mt++) {
                uint32_t row = (uint32_t)(warpM * 32 + mt * 16) + r16;
                LDSM_X4(a_[mt][0], a_[mt][1], a_[mt][2], a_[mt][3],
                        aB + SWZ(row * 128 + koffb));
            }
            uint32_t bh[2][4];
#pragma unroll
            for (int g = 0; g < 2; g++) {
                uint32_t row = (uint32_t)(warpN * 32 + g * 16) + r16;
                LDSM_X4(bh[g][0], bh[g][1], bh[g][2], bh[g][3],
                        yB + SWZ(row * 128 + koffb));
            }
#pragma unroll
            for (int mt = 0; mt < 2; mt++)
#pragma unroll
                for (int g = 0; g < 2; g++) {
                    MMA_F16(acc[mt][2 * g],     a_[mt], bh[g][0], bh[g][2]);
                    MMA_F16(acc[mt][2 * g + 1], a_[mt], bh[g][1], bh[g][3]);
                }
        }
    }

    {
        int c = cnt;
        c += __shfl_xor_sync(0xFFFFFFFFu, c, 1);
        c += __shfl_xor_sync(0xFFFFFFFFu, c, 2);
        if ((lid & 3) == 0) sNorm[r] = (float)(c ? c : 1);
    }
    __syncthreads();

#pragma unroll
    for (int mt = 0; mt < 2; mt++) {
        int lr = warpM * 32 + mt * 16 + (lid >> 2);
        float i0 = 1.0f / sNorm[lr];
        float i1 = 1.0f / sNorm[lr + 8];
        float* o0 = out + ((size_t)(b * E_ + e0 + lr)) * F_;
        float* o1 = o0 + 8 * F_;
#pragma unroll
        for (int nt = 0; nt < 4; nt++) {
            int col = warpN * 32 + nt * 8 + (lid & 3) * 2;
            float2 bb = *(const float2*)(bias + col);
            float* d = acc[mt][nt];
            float2 v0, v1;
            v0.x = fmaxf(fmaf(d[0], i0, bb.x), 0.f);
            v0.y = fmaxf(fmaf(d[1], i0, bb.y), 0.f);
            v1.x = fmaxf(fmaf(d[2], i1, bb.x), 0.f);
            v1.y = fmaxf(fmaf(d[3], i1, bb.y), 0.f);
            *(float2*)(o0 + col) = v0;
            *(float2*)(o1 + col) = v1;
        }
    }
}

extern "C" void kernel_launch(void* const* d_in, const int* in_sizes, int n_in,
                              void* d_out, int out_size) {
    const float* X    = (const float*)d_in[0];  // [B,N,F]
    const float* adj  = (const float*)d_in[1];  // [B,E,N]
    const float* W    = (const float*)d_in[2];  // [F,F]
    const float* bias = (const float*)d_in[3];  // [F]
    float* out = (float*)d_out;                 // [B,E,F]
    (void)in_sizes; (void)n_in; (void)out_size;

    // max(phaseA 48K, phaseB 64K) + 1K align slack
    const int smem_fused = 1024 + 16384 + 3 * 16384;  // 66560
    cudaFuncSetAttribute(v2h_fused, cudaFuncAttributeMaxDynamicSharedMemorySize, smem_fused);

    v2h_clear<<<1, 256>>>();
    v2h_fused<<<256, 256, smem_fused>>>(X, W, adj, bias, out);
}